// round 17
// baseline (speedup 1.0000x reference)
#include <cuda_runtime.h>
#include <math.h>
#include <cstdint>

// ---------------------------------------------------------------------------
// casConv2d — MEASUREMENT ROUND: K1m (tf32 mma, unchanged from R16) + K2,
// padded with 3 idempotent K2 replays so the ncu window (position 6 = call-2
// launch-1 at 5 launches/call) captures k_partials_mma for the first time.
// ---------------------------------------------------------------------------

typedef unsigned long long u64;

__device__ float g_part[1024u * 36u * 128u];   // [l][j][oc]

// ---- f32x2 helpers (K2) ----
__device__ __forceinline__ u64 fma2(u64 a, u64 b, u64 c) {
    u64 d;
    asm("fma.rn.f32x2 %0, %1, %2, %3;" : "=l"(d) : "l"(a), "l"(b), "l"(c));
    return d;
}
__device__ __forceinline__ u64 add2(u64 a, u64 b) {
    u64 d;
    asm("add.rn.f32x2 %0, %1, %2;" : "=l"(d) : "l"(a), "l"(b));
    return d;
}
__device__ __forceinline__ u64 bcast2(float v) {
    u64 d; unsigned u = __float_as_uint(v);
    asm("mov.b64 %0, {%1, %1};" : "=l"(d) : "r"(u));
    return d;
}
__device__ __forceinline__ float2 unpack2(u64 v) {
    float2 f;
    asm("mov.b64 {%0, %1}, %2;" : "=f"(f.x), "=f"(f.y) : "l"(v));
    return f;
}
__device__ __forceinline__ u64 pack2(float x, float y) {
    u64 d;
    asm("mov.b64 %0, {%1, %2};" : "=l"(d) : "f"(x), "f"(y));
    return d;
}

// ---- tf32 helpers ----
__device__ __forceinline__ uint32_t f2tf32(float v) {
    uint32_t r;
    asm("cvt.rna.tf32.f32 %0, %1;" : "=r"(r) : "f"(v));
    return r;
}
__device__ __forceinline__ void mma_tf32(float* d, const uint32_t* a,
                                         const uint32_t* b) {
    asm volatile(
        "mma.sync.aligned.m16n8k8.row.col.f32.tf32.tf32.f32 "
        "{%0,%1,%2,%3}, {%4,%5,%6,%7}, {%8,%9}, {%0,%1,%2,%3};"
        : "+f"(d[0]), "+f"(d[1]), "+f"(d[2]), "+f"(d[3])
        : "r"(a[0]), "r"(a[1]), "r"(a[2]), "r"(a[3]), "r"(b[0]), "r"(b[1]));
}

// ---------------------------------------------------------------------------
// K1m: grid (32, 36), 256 threads (8 warps), one oh per block. (R16, frozen)
// ---------------------------------------------------------------------------
__global__ void __launch_bounds__(256)
k_partials_mma(const float* __restrict__ x, const float* __restrict__ w) {
    __shared__ uint32_t w_s[2][128][36];
    __shared__ uint32_t x_s[2][32][36];

    const int tid  = threadIdx.x;
    const int lane = tid & 31;
    const int wid  = tid >> 5;
    const int oh   = blockIdx.x;
    const int j    = blockIdx.y;
    const int base = j << 5;

#pragma unroll
    for (int k = 0; k < 4; ++k) {
        int e  = tid + (k << 8);
        int oc = e >> 3;
        int q  = e & 7;
        float4 v = *(const float4*)(w + oc * 1152 + base + (q << 2));
        float vv[4] = {v.x, v.y, v.z, v.w};
#pragma unroll
        for (int i = 0; i < 4; ++i) {
            uint32_t hi = f2tf32(vv[i]);
            uint32_t lo = f2tf32(vv[i] - __uint_as_float(hi));
            w_s[0][oc][(q << 2) + i] = hi;
            w_s[1][oc][(q << 2) + i] = lo;
        }
    }

    {
        const int idx = base + lane;
        const int c   = idx / 9;
        const int rm  = idx - c * 9;
        const int kh  = rm / 3;
        const int kw  = rm - kh * 3;
        const int gh  = oh - 1 + kh;
        const bool hok = (unsigned)gh < 32u;
        const int xb  = (c << 10) + (gh << 5);
#pragma unroll
        for (int i = 0; i < 4; ++i) {
            const int l  = (wid << 2) + i;
            const int gw = l - 1 + kw;
            float v = 0.0f;
            if (hok && (unsigned)gw < 32u) v = x[xb + gw];
            uint32_t hi = f2tf32(v);
            uint32_t lo = f2tf32(v - __uint_as_float(hi));
            x_s[0][l][lane] = hi;
            x_s[1][l][lane] = lo;
        }
    }
    __syncthreads();

    uint32_t B[2][2][4][2];
    const int bn = (wid << 4) + (lane >> 2);
    const int bk = lane & 3;
#pragma unroll
    for (int s = 0; s < 2; ++s)
#pragma unroll
        for (int nt = 0; nt < 2; ++nt)
#pragma unroll
            for (int k = 0; k < 4; ++k) {
                B[s][nt][k][0] = w_s[s][bn + nt * 8][k * 8 + bk];
                B[s][nt][k][1] = w_s[s][bn + nt * 8][k * 8 + bk + 4];
            }

    const int ar = lane >> 2;
    const int ac = lane & 3;

#pragma unroll
    for (int mt = 0; mt < 2; ++mt) {
        float acc[2][4] = {};
#pragma unroll
        for (int k = 0; k < 4; ++k) {
            uint32_t ah[4], al[4];
            const int r0 = mt * 16 + ar;
            const int c0 = k * 8 + ac;
            ah[0] = x_s[0][r0][c0];
            ah[1] = x_s[0][r0 + 8][c0];
            ah[2] = x_s[0][r0][c0 + 4];
            ah[3] = x_s[0][r0 + 8][c0 + 4];
            al[0] = x_s[1][r0][c0];
            al[1] = x_s[1][r0 + 8][c0];
            al[2] = x_s[1][r0][c0 + 4];
            al[3] = x_s[1][r0 + 8][c0 + 4];
#pragma unroll
            for (int nt = 0; nt < 2; ++nt) {
                mma_tf32(acc[nt], ah, B[0][nt][k]);   // xhi * whi
                mma_tf32(acc[nt], ah, B[1][nt][k]);   // xhi * wlo
                mma_tf32(acc[nt], al, B[0][nt][k]);   // xlo * whi
            }
        }
        const int lA = (oh << 5) + mt * 16 + ar;
#pragma unroll
        for (int nt = 0; nt < 2; ++nt) {
            const int oc0 = (wid << 4) + nt * 8 + (ac << 1);
            float* p0 = g_part + (size_t)lA * 4608 + (j << 7) + oc0;
            float* p1 = g_part + (size_t)(lA + 8) * 4608 + (j << 7) + oc0;
            *(float2*)p0 = make_float2(acc[nt][0], acc[nt][1]);
            *(float2*)p1 = make_float2(acc[nt][2], acc[nt][3]);
        }
    }
}

// ---------------------------------------------------------------------------
// K2: block (128 thr, 4 warps) per l; grid = 1024. (R13 version, unchanged)
// ---------------------------------------------------------------------------
__global__ void __launch_bounds__(128)
k_quant(const float* __restrict__ bias, float* __restrict__ out) {
    const int tid  = threadIdx.x;
    const int lane = tid & 31;
    const int wid  = tid >> 5;
    const int l    = blockIdx.x;
    const int j0   = wid * 9;

    const longlong2* bp =
        (const longlong2*)(g_part + (size_t)l * 4608) + lane;

    __shared__ longlong2 s[4][32];

    longlong2 pv[9];
    u64 t0 = 0ull, t1 = 0ull;
#pragma unroll
    for (int j = 0; j < 9; ++j) {
        pv[j] = bp[(j0 + j) * 32];
        t0 = add2(t0, (u64)pv[j].x);
        t1 = add2(t1, (u64)pv[j].y);
    }
    s[wid][lane] = make_longlong2((long long)t0, (long long)t1);
    __syncthreads();

    longlong2 bb = ((const longlong2*)bias)[lane];
    u64 tot0 = (u64)bb.x, tot1 = (u64)bb.y;
#pragma unroll
    for (int w2 = 0; w2 < 4; ++w2) {
        longlong2 v = s[w2][lane];
        tot0 = add2(tot0, (u64)v.x);
        tot1 = add2(tot1, (u64)v.y);
    }
    float2 f0 = unpack2(tot0), f1 = unpack2(tot1);
    float mx = fmaxf(fmaxf(f0.x, f0.y), fmaxf(f1.x, f1.y));
    float mn = fminf(fminf(f0.x, f0.y), fminf(f1.x, f1.y));
#pragma unroll
    for (int sft = 16; sft > 0; sft >>= 1) {
        mx = fmaxf(mx, __shfl_xor_sync(0xffffffffu, mx, sft));
        mn = fminf(mn, __shfl_xor_sync(0xffffffffu, mn, sft));
    }

    const float sc = (mx - mn) * (1.0f / 255.0f);
    float z = -mn / sc;                              // inf/nan if sc==0
    z = fminf(fmaxf(z, 0.0f), 255.0f);               // clip (nan -> 0)
    if (isnan(z)) z = 0.0f;
    const float zp  = truncf(z);                     // .int() truncation
    const float rcp = 1.0f / sc;

    const float MAGIC = 12582912.0f;                 // 1.5 * 2^23
    const u64 rcp2 = bcast2(rcp);
    const u64 mg2  = bcast2(MAGIC);
    const u64 zm2  = bcast2(zp - MAGIC);

    float ox = 0.f, oy = 0.f, oz = 0.f, ow = 0.f;
#pragma unroll
    for (int j = 0; j < 9; ++j) {
        u64 r0 = add2(fma2((u64)pv[j].x, rcp2, mg2), zm2);  // rint(v/sc)+zp
        u64 r1 = add2(fma2((u64)pv[j].y, rcp2, mg2), zm2);
        float2 c0 = unpack2(r0), c1 = unpack2(r1);
        ox += fminf(fmaxf(c0.x, 0.0f), 255.0f);
        oy += fminf(fmaxf(c0.y, 0.0f), 255.0f);
        oz += fminf(fmaxf(c1.x, 0.0f), 255.0f);
        ow += fminf(fmaxf(c1.y, 0.0f), 255.0f);
    }
    __syncthreads();
    s[wid][lane] = make_longlong2((long long)pack2(ox, oy),
                                  (long long)pack2(oz, ow));
    __syncthreads();

    const float* sf = (const float*)s;               // [warp][128 oc]
    float v = sf[tid] + sf[128 + tid] + sf[256 + tid] + sf[384 + tid];
    out[(tid << 10) + l] = (v - 36.0f * zp) * sc;
}

// ---------------------------------------------------------------------------
extern "C" void kernel_launch(void* const* d_in, const int* in_sizes, int n_in,
                              void* d_out, int out_size) {
    const float *x = nullptr, *w = nullptr, *b = nullptr;
    for (int i = 0; i < n_in; ++i) {
        if      (in_sizes[i] == 131072) x = (const float*)d_in[i];  // 128*32*32
        else if (in_sizes[i] == 147456) w = (const float*)d_in[i];  // 128*128*9
        else if (in_sizes[i] == 128)    b = (const float*)d_in[i];
    }
    k_partials_mma<<<dim3(32, 36), 256>>>(x, w);
    k_quant<<<1024, 128>>>(b, (float*)d_out);
    // Idempotent pads -> 5 launches/call -> ncu position 6 = k_partials_mma.
    k_quant<<<1024, 128>>>(b, (float*)d_out);
    k_quant<<<1024, 128>>>(b, (float*)d_out);
    k_quant<<<1024, 128>>>(b, (float*)d_out);
}